// round 4
// baseline (speedup 1.0000x reference)
#include <cuda_runtime.h>
#include <cstdint>

// SigmaModel: h = relu([s,a] @ W1^T + b1); tri = h @ W2^T + b2;
// out[b,i,j] = tri[t(min(i,j),max(i,j))], diag -> exp.
// f32x2 GEMM, broadcast-friendly tiling: 128 rows/CTA, warp = 64r x 72c.

#define BATCH    131072
#define SDIM     32
#define ADIM     8
#define INDIM    40
#define HID      64
#define TRI      528
#define ROWS     128
#define NT       512
#define NPAD     580         // W2 k-major stride (mult of 4 for LDS.128)
#define HPAD     65          // H row stride (odd -> banked row-groups)
#define XPAD     41
#define TPAD     578         // tri buffer stride (even, mod32=2)

// shared memory layout (float offsets)
#define SM_W2    0           // [64][NPAD] = 37120 ; aliased as tri buf [64][TPAD] later
#define SM_H     37120       // [128][HPAD] = 8320
#define SM_X     45440       // [128][XPAD] = 5248
#define SM_W1    50688       // [40][64] transposed = 2560
#define SM_B1    53248       // [64]
#define SM_B2    53312       // [576]
#define SM_TBL   53888       // int[1024]
#define SM_FLOATS 54912      // 219648 bytes

typedef unsigned long long u64;

__device__ __forceinline__ u64 pack2(float lo, float hi) {
    u64 r; asm("mov.b64 %0, {%1, %2};" : "=l"(r) : "f"(lo), "f"(hi)); return r;
}
__device__ __forceinline__ void unpack2(u64 v, float& lo, float& hi) {
    asm("mov.b64 {%0, %1}, %2;" : "=f"(lo), "=f"(hi) : "l"(v));
}
__device__ __forceinline__ void fma2(u64& d, u64 a, u64 b) {
    asm("fma.rn.f32x2 %0, %1, %2, %0;" : "+l"(d) : "l"(a), "l"(b));
}

__global__ void __launch_bounds__(NT, 1)
sigma_fused_kernel(const float* __restrict__ s,
                   const float* __restrict__ a,
                   const float* __restrict__ W1,
                   const float* __restrict__ b1,
                   const float* __restrict__ W2,
                   const float* __restrict__ b2,
                   float* __restrict__ out) {
    extern __shared__ float smem[];
    float* sW2 = smem + SM_W2;
    float* sH  = smem + SM_H;
    float* sX  = smem + SM_X;
    float* sW1 = smem + SM_W1;
    float* sB1 = smem + SM_B1;
    float* sB2 = smem + SM_B2;
    int*   sTbl = (int*)(smem + SM_TBL);

    const int tid  = threadIdx.x;
    const int row0 = blockIdx.x * ROWS;

    // ---------------- Phase 0: staging ----------------
    // W2[t][k] -> sW2[k][t] (coalesced LDG; STS ~4-way, one-time)
    for (int idx = tid; idx < TRI * HID; idx += NT) {
        int t = idx >> 6, k = idx & 63;
        sW2[k * NPAD + t] = W2[idx];
    }
    // zero-pad cols [TRI, NPAD)
    for (int idx = tid; idx < HID * (NPAD - TRI); idx += NT) {
        int k = idx / (NPAD - TRI), t = TRI + (idx - k * (NPAD - TRI));
        sW2[k * NPAD + t] = 0.0f;
    }
    for (int idx = tid; idx < ROWS * SDIM; idx += NT) {
        int r = idx >> 5, c = idx & 31;
        sX[r * XPAD + c] = s[(size_t)row0 * SDIM + idx];
    }
    for (int idx = tid; idx < ROWS * ADIM; idx += NT) {
        int r = idx >> 3, c = idx & 7;
        sX[r * XPAD + SDIM + c] = a[(size_t)row0 * ADIM + idx];
    }
    for (int idx = tid; idx < HID * INDIM; idx += NT) {
        int hh = idx / INDIM, k = idx - hh * INDIM;
        sW1[k * HID + hh] = W1[idx];
    }
    if (tid < HID) sB1[tid] = b1[tid];
    for (int idx = tid; idx < 576; idx += NT)
        sB2[idx] = (idx < TRI) ? b2[idx] : 0.0f;
    for (int o = tid; o < 1024; o += NT) {
        int i = o >> 5, j = o & 31;
        int ii = (i < j) ? i : j;
        int jj = (i < j) ? j : i;
        int t = ii * 32 - ((ii * (ii + 1)) >> 1) + jj;
        sTbl[o] = t | ((i == j) ? (1 << 16) : 0);
    }
    __syncthreads();

    // ---------------- Phase 1: H = relu(X @ W1^T + b1), f32x2 ---------------
    {
        const int r  = tid >> 2;            // 0..127
        const int hg = (tid & 3) * 16;      // 16 hidden cols = 8 pairs
        u64 acc[8];
#pragma unroll
        for (int u = 0; u < 8; ++u)
            acc[u] = *reinterpret_cast<const u64*>(&sB1[hg + 2 * u]);
        const float* xrow = &sX[r * XPAD];
#pragma unroll 5
        for (int k = 0; k < INDIM; ++k) {
            u64 xb = pack2(xrow[k], xrow[k]);
            const ulonglong2 w0 = *reinterpret_cast<const ulonglong2*>(&sW1[k * HID + hg]);
            const ulonglong2 w1 = *reinterpret_cast<const ulonglong2*>(&sW1[k * HID + hg + 4]);
            const ulonglong2 w2 = *reinterpret_cast<const ulonglong2*>(&sW1[k * HID + hg + 8]);
            const ulonglong2 w3 = *reinterpret_cast<const ulonglong2*>(&sW1[k * HID + hg + 12]);
            fma2(acc[0], xb, w0.x); fma2(acc[1], xb, w0.y);
            fma2(acc[2], xb, w1.x); fma2(acc[3], xb, w1.y);
            fma2(acc[4], xb, w2.x); fma2(acc[5], xb, w2.y);
            fma2(acc[6], xb, w3.x); fma2(acc[7], xb, w3.y);
        }
        float* hrow = &sH[r * HPAD + hg];
#pragma unroll
        for (int u = 0; u < 8; ++u) {
            float lo, hi; unpack2(acc[u], lo, hi);
            hrow[2 * u]     = fmaxf(lo, 0.0f);
            hrow[2 * u + 1] = fmaxf(hi, 0.0f);
        }
    }
    __syncthreads();

    // ---------------- Phase 2: tri = H @ W2^T + b2 ---------------------------
    // 16 warps = 2 row-blocks x 8 col-blocks(72 cols). Lane: rg=lane&7, cg=lane>>3.
    // Thread rows: rb*64 + rg + 8m (m=0..7). Thread cols: 4 float4 chunks at
    // cb*72 + 16q + 4cg (pairs 2q,2q+1) + tail pair at cb*72 + 64 + 2cg.
    const int wi   = tid >> 5, lane = tid & 31;
    const int rb   = wi >> 3,  cb   = wi & 7;
    const int rg   = lane & 7, cg   = lane >> 3;
    const int wcol = cb * 72;

    u64 acc2[8][9];
#pragma unroll
    for (int q = 0; q < 4; ++q)
#pragma unroll
        for (int h2 = 0; h2 < 2; ++h2) {
            u64 b = *reinterpret_cast<const u64*>(&sB2[wcol + 16 * q + 4 * cg + 2 * h2]);
#pragma unroll
            for (int m = 0; m < 8; ++m) acc2[m][2 * q + h2] = b;
        }
    {
        u64 b = *reinterpret_cast<const u64*>(&sB2[wcol + 64 + 2 * cg]);
#pragma unroll
        for (int m = 0; m < 8; ++m) acc2[m][8] = b;
    }

    const float* hbase = &sH[(rb * 64 + rg) * HPAD];
#pragma unroll 1
    for (int k = 0; k < HID; ++k) {
        const float* wr = &sW2[k * NPAD + wcol];
        // 5 broadcast loads (each 1 wavefront)
        const ulonglong2 q0 = *reinterpret_cast<const ulonglong2*>(wr + 4 * cg);
        const ulonglong2 q1 = *reinterpret_cast<const ulonglong2*>(wr + 16 + 4 * cg);
        const ulonglong2 q2 = *reinterpret_cast<const ulonglong2*>(wr + 32 + 4 * cg);
        const ulonglong2 q3 = *reinterpret_cast<const ulonglong2*>(wr + 48 + 4 * cg);
        const u64 qt = *reinterpret_cast<const u64*>(wr + 64 + 2 * cg);
        // 8 banked h loads (1 wavefront each)
        u64 hb[8];
#pragma unroll
        for (int m = 0; m < 8; ++m) {
            float hv = hbase[m * 8 * HPAD + k];
            hb[m] = pack2(hv, hv);
        }
#pragma unroll
        for (int m = 0; m < 8; ++m) {
            fma2(acc2[m][0], hb[m], q0.x);
            fma2(acc2[m][1], hb[m], q0.y);
            fma2(acc2[m][2], hb[m], q1.x);
            fma2(acc2[m][3], hb[m], q1.y);
            fma2(acc2[m][4], hb[m], q2.x);
            fma2(acc2[m][5], hb[m], q2.y);
            fma2(acc2[m][6], hb[m], q3.x);
            fma2(acc2[m][7], hb[m], q3.y);
            fma2(acc2[m][8], hb[m], qt);
        }
    }

    __syncthreads();          // all GEMM reads of sW2 done -> alias as tri buffer
    float* sTri = sW2;        // [64][TPAD]

    const int4* tbl4 = reinterpret_cast<const int4*>(sTbl);

#pragma unroll
    for (int hf = 0; hf < 2; ++hf) {
        if (rb == hf) {
#pragma unroll
            for (int m = 0; m < 8; ++m) {
                float* trow = &sTri[(rg + 8 * m) * TPAD + wcol];
#pragma unroll
                for (int q = 0; q < 4; ++q) {
                    *reinterpret_cast<u64*>(trow + 16 * q + 4 * cg)     = acc2[m][2 * q];
                    *reinterpret_cast<u64*>(trow + 16 * q + 4 * cg + 2) = acc2[m][2 * q + 1];
                }
                *reinterpret_cast<u64*>(trow + 64 + 2 * cg) = acc2[m][8];
            }
        }
        __syncthreads();

        // scatter 64 rows -> out
        float4* out4 = reinterpret_cast<float4*>(out + (size_t)(row0 + hf * 64) * 1024);
        for (int idx = tid; idx < 64 * 256; idx += NT) {
            const int r  = idx >> 8;
            const int o4 = idx & 255;
            const int4 tt = tbl4[o4];
            const float* tr = &sTri[r * TPAD];
            float v0 = tr[tt.x & 0xffff];
            float v1 = tr[tt.y & 0xffff];
            float v2 = tr[tt.z & 0xffff];
            float v3 = tr[tt.w & 0xffff];
            if (tt.x >> 16) v0 = __expf(v0);
            if (tt.y >> 16) v1 = __expf(v1);
            if (tt.z >> 16) v2 = __expf(v2);
            if (tt.w >> 16) v3 = __expf(v3);
            out4[idx] = make_float4(v0, v1, v2, v3);
        }
        __syncthreads();
    }
}

extern "C" void kernel_launch(void* const* d_in, const int* in_sizes, int n_in,
                              void* d_out, int out_size) {
    (void)in_sizes; (void)n_in; (void)out_size;
    const float* s  = (const float*)d_in[0];
    const float* a  = (const float*)d_in[1];
    const float* W1 = (const float*)d_in[2];
    const float* b1 = (const float*)d_in[3];
    const float* W2 = (const float*)d_in[4];
    const float* b2 = (const float*)d_in[5];
    float* out = (float*)d_out;

    const size_t smem_bytes = SM_FLOATS * sizeof(float);  // 219648
    cudaFuncSetAttribute(sigma_fused_kernel,
                         cudaFuncAttributeMaxDynamicSharedMemorySize,
                         (int)smem_bytes);
    sigma_fused_kernel<<<BATCH / ROWS, NT, smem_bytes>>>(s, a, W1, b1, W2, b2, out);
}

// round 5
// speedup vs baseline: 5.3712x; 5.3712x over previous
#include <cuda_runtime.h>
#include <cstdint>

// SigmaModel: h = relu([s,a] @ W1^T + b1); tri = h @ W2^T + b2;
// out[b,i,j] = tri[t(min(i,j),max(i,j))], diag -> exp.
// f32x2 GEMM with broadcast W2 loads; 64 rows/CTA, warp tile 32r x 72c,
// thread tile 4r x 18c (72 f32 accs = 72 regs, fits 128-reg cap).

#define BATCH    131072
#define SDIM     32
#define ADIM     8
#define INDIM    40
#define HID      64
#define TRI      528
#define ROWS     64
#define NT       512
#define NPAD     580         // W2 k-major stride (mult of 4: LDS.128-aligned)
#define HPAD     65          // H row stride (65 mod 32 == 1 -> banked rows)
#define XPAD     41
#define TPAD     578         // tri buffer stride

// shared memory layout (float offsets)
#define SM_W2    0           // [64][NPAD]=37120; aliased as tri buf [64][TPAD]
#define SM_H     37120       // [64][HPAD]=4160
#define SM_X     41280       // [64][XPAD]=2624
#define SM_W1    43904       // [40][64] transposed = 2560
#define SM_B1    46464       // [64]
#define SM_B2    46528       // [576]
#define SM_TBL   47104       // int[1024]
#define SM_FLOATS 48128      // 192512 bytes

typedef unsigned long long u64;

__device__ __forceinline__ u64 pack2(float lo, float hi) {
    u64 r; asm("mov.b64 %0, {%1, %2};" : "=l"(r) : "f"(lo), "f"(hi)); return r;
}
__device__ __forceinline__ void unpack2(u64 v, float& lo, float& hi) {
    asm("mov.b64 {%0, %1}, %2;" : "=f"(lo), "=f"(hi) : "l"(v));
}
__device__ __forceinline__ void fma2(u64& d, u64 a, u64 b) {
    asm("fma.rn.f32x2 %0, %1, %2, %0;" : "+l"(d) : "l"(a), "l"(b));
}

__global__ void __launch_bounds__(NT, 1)
sigma_fused_kernel(const float* __restrict__ s,
                   const float* __restrict__ a,
                   const float* __restrict__ W1,
                   const float* __restrict__ b1,
                   const float* __restrict__ W2,
                   const float* __restrict__ b2,
                   float* __restrict__ out) {
    extern __shared__ float smem[];
    float* sW2 = smem + SM_W2;
    float* sH  = smem + SM_H;
    float* sX  = smem + SM_X;
    float* sW1 = smem + SM_W1;
    float* sB1 = smem + SM_B1;
    float* sB2 = smem + SM_B2;
    int*   sTbl = (int*)(smem + SM_TBL);

    const int tid  = threadIdx.x;
    const int row0 = blockIdx.x * ROWS;

    // ---------------- Phase 0: staging ----------------
    // W2[t][k] -> sW2[k][t]  (coalesced LDG; one-time STS conflicts OK)
    for (int idx = tid; idx < TRI * HID; idx += NT) {
        int t = idx >> 6, k = idx & 63;
        sW2[k * NPAD + t] = W2[idx];
    }
    for (int idx = tid; idx < HID * (NPAD - TRI); idx += NT) {
        int k = idx / (NPAD - TRI), t = TRI + (idx - k * (NPAD - TRI));
        sW2[k * NPAD + t] = 0.0f;
    }
    for (int idx = tid; idx < ROWS * SDIM; idx += NT) {
        int r = idx >> 5, c = idx & 31;
        sX[r * XPAD + c] = s[(size_t)row0 * SDIM + idx];
    }
    for (int idx = tid; idx < ROWS * ADIM; idx += NT) {
        int r = idx >> 3, c = idx & 7;
        sX[r * XPAD + SDIM + c] = a[(size_t)row0 * ADIM + idx];
    }
    for (int idx = tid; idx < HID * INDIM; idx += NT) {
        int hh = idx / INDIM, k = idx - hh * INDIM;
        sW1[k * HID + hh] = W1[idx];
    }
    if (tid < HID) sB1[tid] = b1[tid];
    for (int idx = tid; idx < 576; idx += NT)
        sB2[idx] = (idx < TRI) ? b2[idx] : 0.0f;
    for (int o = tid; o < 1024; o += NT) {
        int i = o >> 5, j = o & 31;
        int ii = (i < j) ? i : j;
        int jj = (i < j) ? j : i;
        int t = ii * 32 - ((ii * (ii + 1)) >> 1) + jj;
        sTbl[o] = t | ((i == j) ? (1 << 16) : 0);
    }
    __syncthreads();

    // ---------------- Phase 1: H = relu(X @ W1^T + b1), f32x2 ---------------
    {
        const int r  = tid >> 3;           // 0..63
        const int hg = (tid & 7) * 8;      // 8 hidden cols = 4 pairs
        u64 acc[4];
#pragma unroll
        for (int u = 0; u < 4; ++u)
            acc[u] = *reinterpret_cast<const u64*>(&sB1[hg + 2 * u]);
        const float* xrow = &sX[r * XPAD];
#pragma unroll 5
        for (int k = 0; k < INDIM; ++k) {
            u64 xb = pack2(xrow[k], xrow[k]);
            const ulonglong2 w0 = *reinterpret_cast<const ulonglong2*>(&sW1[k * HID + hg]);
            const ulonglong2 w1 = *reinterpret_cast<const ulonglong2*>(&sW1[k * HID + hg + 4]);
            fma2(acc[0], xb, w0.x); fma2(acc[1], xb, w0.y);
            fma2(acc[2], xb, w1.x); fma2(acc[3], xb, w1.y);
        }
        float* hrow = &sH[r * HPAD + hg];
#pragma unroll
        for (int u = 0; u < 4; ++u) {
            float lo, hi; unpack2(acc[u], lo, hi);
            hrow[2 * u]     = fmaxf(lo, 0.0f);
            hrow[2 * u + 1] = fmaxf(hi, 0.0f);
        }
    }
    __syncthreads();

    // ---------------- Phase 2: tri = H @ W2^T + b2 ---------------------------
    // 16 warps = 2 row-blocks(32r) x 8 col-blocks(72c).
    // Lane: rg = lane&7 (row group), cg = lane>>3 (col group).
    // Thread rows: rb*32 + rg + 8m (m=0..3). Thread cols: quads 16q+4cg (q=0..3)
    // + tail pair 64+2cg, all relative to wcol = cb*72.
    const int wi   = tid >> 5, lane = tid & 31;
    const int rb   = wi >> 3,  cb   = wi & 7;
    const int rg   = lane & 7, cg   = lane >> 3;
    const int wcol = cb * 72;

    u64 acc2[4][9];
#pragma unroll
    for (int q = 0; q < 4; ++q) {
        u64 blo = *reinterpret_cast<const u64*>(&sB2[wcol + 16 * q + 4 * cg]);
        u64 bhi = *reinterpret_cast<const u64*>(&sB2[wcol + 16 * q + 4 * cg + 2]);
#pragma unroll
        for (int m = 0; m < 4; ++m) { acc2[m][2 * q] = blo; acc2[m][2 * q + 1] = bhi; }
    }
    {
        u64 bt = *reinterpret_cast<const u64*>(&sB2[wcol + 64 + 2 * cg]);
#pragma unroll
        for (int m = 0; m < 4; ++m) acc2[m][8] = bt;
    }

    const float* hbase = &sH[(rb * 32 + rg) * HPAD];
#pragma unroll 1
    for (int k = 0; k < HID; ++k) {
        const float* wr = &sW2[k * NPAD + wcol];
        // 5 broadcast w loads (1 wavefront each)
        const ulonglong2 q0 = *reinterpret_cast<const ulonglong2*>(wr + 4 * cg);
        const ulonglong2 q1 = *reinterpret_cast<const ulonglong2*>(wr + 16 + 4 * cg);
        const ulonglong2 q2 = *reinterpret_cast<const ulonglong2*>(wr + 32 + 4 * cg);
        const ulonglong2 q3 = *reinterpret_cast<const ulonglong2*>(wr + 48 + 4 * cg);
        const u64 qt = *reinterpret_cast<const u64*>(wr + 64 + 2 * cg);
        // 4 banked h loads (1 wavefront each)
        u64 hb[4];
#pragma unroll
        for (int m = 0; m < 4; ++m) {
            float hv = hbase[m * 8 * HPAD + k];
            hb[m] = pack2(hv, hv);
        }
#pragma unroll
        for (int m = 0; m < 4; ++m) {
            fma2(acc2[m][0], hb[m], q0.x);
            fma2(acc2[m][1], hb[m], q0.y);
            fma2(acc2[m][2], hb[m], q1.x);
            fma2(acc2[m][3], hb[m], q1.y);
            fma2(acc2[m][4], hb[m], q2.x);
            fma2(acc2[m][5], hb[m], q2.y);
            fma2(acc2[m][6], hb[m], q3.x);
            fma2(acc2[m][7], hb[m], q3.y);
            fma2(acc2[m][8], hb[m], qt);
        }
    }

    __syncthreads();          // all GEMM reads of sW2 done -> alias as tri buffer
    float* sTri = sW2;        // [64][TPAD]

    // write accumulators to tri buffer
#pragma unroll
    for (int m = 0; m < 4; ++m) {
        float* trow = &sTri[(rb * 32 + rg + 8 * m) * TPAD + wcol];
#pragma unroll
        for (int q = 0; q < 4; ++q) {
            *reinterpret_cast<u64*>(trow + 16 * q + 4 * cg)     = acc2[m][2 * q];
            *reinterpret_cast<u64*>(trow + 16 * q + 4 * cg + 2) = acc2[m][2 * q + 1];
        }
        *reinterpret_cast<u64*>(trow + 64 + 2 * cg) = acc2[m][8];
    }
    __syncthreads();

    // ---------------- Phase 3: scatter to symmetrized 32x32, exp diag -------
    const int4* tbl4 = reinterpret_cast<const int4*>(sTbl);
    float4* out4 = reinterpret_cast<float4*>(out + (size_t)row0 * 1024);
    for (int idx = tid; idx < ROWS * 256; idx += NT) {
        const int r  = idx >> 8;
        const int o4 = idx & 255;
        const int4 tt = tbl4[o4];
        const float* tr = &sTri[r * TPAD];
        float v0 = tr[tt.x & 0xffff];
        float v1 = tr[tt.y & 0xffff];
        float v2 = tr[tt.z & 0xffff];
        float v3 = tr[tt.w & 0xffff];
        if (tt.x >> 16) v0 = __expf(v0);
        if (tt.y >> 16) v1 = __expf(v1);
        if (tt.z >> 16) v2 = __expf(v2);
        if (tt.w >> 16) v3 = __expf(v3);
        out4[idx] = make_float4(v0, v1, v2, v3);
    }
}

extern "C" void kernel_launch(void* const* d_in, const int* in_sizes, int n_in,
                              void* d_out, int out_size) {
    (void)in_sizes; (void)n_in; (void)out_size;
    const float* s  = (const float*)d_in[0];
    const float* a  = (const float*)d_in[1];
    const float* W1 = (const float*)d_in[2];
    const float* b1 = (const float*)d_in[3];
    const float* W2 = (const float*)d_in[4];
    const float* b2 = (const float*)d_in[5];
    float* out = (float*)d_out;

    const size_t smem_bytes = SM_FLOATS * sizeof(float);  // 192512
    cudaFuncSetAttribute(sigma_fused_kernel,
                         cudaFuncAttributeMaxDynamicSharedMemorySize,
                         (int)smem_bytes);
    sigma_fused_kernel<<<BATCH / ROWS, NT, smem_bytes>>>(s, a, W1, b1, W2, b2, out);
}